// round 2
// baseline (speedup 1.0000x reference)
#include <cuda_runtime.h>
#include <stdint.h>

#define NT 256
#define TILE_PTS 128
#define KJ 192            // 32 k * 6 monomials

// Packed f32x2 FMA — only reachable via PTX (ptxas never fuses to FFMA2).
__device__ __forceinline__ unsigned long long fma2(unsigned long long a,
                                                   unsigned long long b,
                                                   unsigned long long c) {
    unsigned long long d;
    asm("fma.rn.f32x2 %0, %1, %2, %3;" : "=l"(d) : "l"(a), "l"(b), "l"(c));
    return d;
}

extern __shared__ __align__(16) float smem[];
// smem layout:
//   M  : [192][128] float  @ 0        (98304 B)  — monomials, xor-swizzled cols
//   P2 : [192][32] float2  @ 98304    (49152 B)  — folded weights, duplicated
//   stage[128][32] reuses the M region for the epilogue.
#define SMEM_BYTES (KJ * TILE_PTS * 4 + KJ * 32 * 8)

__global__ void __launch_bounds__(NT, 1)
hermite_gemm(const float* __restrict__ mlp,
             const float* __restrict__ cd,
             const float* __restrict__ sig,
             const float* __restrict__ gw,
             const float* __restrict__ W,
             float* __restrict__ out,
             int total /* B*N */) {
    float*  M  = smem;
    float2* P2 = reinterpret_cast<float2*>(smem + KJ * TILE_PTS);

    const int tid   = threadIdx.x;
    const int tile0 = blockIdx.x * TILE_PTS;

    // ---- Build P2 (fold sigmas into rbf_weights; duplicate for f32x2) ----
    for (int i = tid; i < KJ * 32; i += NT) {
        int o  = i & 31;
        int kj = i >> 5;
        int k  = kj / 6;
        int j  = kj - k * 6;
        float val = 0.0f;
        if (o < 31) {
            float s   = sig[k];
            float s2  = s * s;
            float is2 = 1.0f / (s2 + 1e-6f);
            float is4 = 1.0f / (s2 * s2 + 1e-6f);
            const float* Wk = W + k * 186 + o;      // [k][h][o], H=6, O=31
            if      (j == 0) val = Wk[0] - is2 * (Wk[93] + Wk[155]);
            else if (j == 1) val = -is2 * Wk[62];   // * g*dx
            else if (j == 2) val = -is2 * Wk[31];   // * g*dy
            else if (j == 3) val = is4 * Wk[155];   // * g*dx^2
            else if (j == 4) val = is4 * Wk[124];   // * g*dx*dy
            else             val = is4 * Wk[93];    // * g*dy^2
        }
        P2[kj * 32 + o] = make_float2(val, val);
    }

    // ---- Phase 1: monomials M[k*6+j][pt ^ (k<<2)] ----
    // Lanes cover k (coalesced gmem); XOR column swizzle keeps the scatter
    // STS <=4-way conflicted while preserving 16B contiguity for phase 2.
#pragma unroll
    for (int it = 0; it < (TILE_PTS * 32) / NT; it++) {   // 16 items
        int item = tid + it * NT;
        int pt   = item >> 5;
        int k    = item & 31;
        int n    = tile0 + pt;
        float dx = 0.0f, dy = 0.0f, g = 0.0f;
        if (n < total) {
            float2 c = reinterpret_cast<const float2*>(cd)[(size_t)n * 32 + k];
            dx = c.x; dy = c.y;
            g  = gw[(size_t)n * 32 + k];
        }
        float m1 = g * dx, m2 = g * dy;
        int col  = pt ^ (k << 2);
        float* Mr = M + (k * 6) * TILE_PTS + col;
        Mr[0 * TILE_PTS] = g;
        Mr[1 * TILE_PTS] = m1;
        Mr[2 * TILE_PTS] = m2;
        Mr[3 * TILE_PTS] = m1 * dx;
        Mr[4 * TILE_PTS] = m1 * dy;
        Mr[5 * TILE_PTS] = m2 * dy;
    }
    __syncthreads();

    // ---- Phase 2: register-blocked GEMM, 4 pts x 4 o per thread ----
    const int og  = tid & 7;        // o-group: outputs og*4 .. og*4+3
    const int pg4 = (tid >> 3) * 4; // first of 4 consecutive points

    unsigned long long acc[2][4];
#pragma unroll
    for (int pp = 0; pp < 2; pp++)
#pragma unroll
        for (int oo = 0; oo < 4; oo++) acc[pp][oo] = 0ull;

    const float2* Pbase = P2 + og * 4;

#pragma unroll 2
    for (int k = 0; k < 32; k++) {
        const float* Mk = M + (k * 6) * TILE_PTS + (pg4 ^ (k << 2));
        const float2* Pk = Pbase + (k * 6) * 32;
#pragma unroll
        for (int j = 0; j < 6; j++) {
            // M float4 = 4 consecutive points = two pre-packed f32x2 pairs.
            ulonglong2 mv = *reinterpret_cast<const ulonglong2*>(Mk + j * TILE_PTS);
            ulonglong2 pv0 = *reinterpret_cast<const ulonglong2*>(Pk + j * 32);
            ulonglong2 pv1 = *reinterpret_cast<const ulonglong2*>(Pk + j * 32 + 2);
            acc[0][0] = fma2(mv.x, pv0.x, acc[0][0]);
            acc[0][1] = fma2(mv.x, pv0.y, acc[0][1]);
            acc[0][2] = fma2(mv.x, pv1.x, acc[0][2]);
            acc[0][3] = fma2(mv.x, pv1.y, acc[0][3]);
            acc[1][0] = fma2(mv.y, pv0.x, acc[1][0]);
            acc[1][1] = fma2(mv.y, pv0.y, acc[1][1]);
            acc[1][2] = fma2(mv.y, pv1.x, acc[1][2]);
            acc[1][3] = fma2(mv.y, pv1.y, acc[1][3]);
        }
    }

    // ---- Epilogue: stage mix into dead M region, then coalesced I/O ----
    __syncthreads();   // all reads of M done
    float* stage = M;  // [128][32]
#pragma unroll
    for (int pp = 0; pp < 2; pp++)
#pragma unroll
        for (int oo = 0; oo < 4; oo++) {
            unsigned long long a = acc[pp][oo];
            float lo = __uint_as_float((unsigned)(a & 0xffffffffu));
            float hi = __uint_as_float((unsigned)(a >> 32));
            int o = og * 4 + oo;
            stage[(pg4 + 2 * pp)     * 32 + o] = lo;   // point pg4+2pp
            stage[(pg4 + 2 * pp + 1) * 32 + o] = hi;   // point pg4+2pp+1
        }
    __syncthreads();

    size_t lim  = (size_t)total * 31;
    size_t base = (size_t)tile0 * 31;
    for (int e = tid; e < TILE_PTS * 31; e += NT) {
        size_t gidx = base + e;
        if (gidx < lim) {
            int rr = e / 31;          // magic-number mul
            int o  = e - rr * 31;
            out[gidx] = mlp[gidx] * stage[rr * 32 + o];
        }
    }
}

extern "C" void kernel_launch(void* const* d_in, const int* in_sizes, int n_in,
                              void* d_out, int out_size) {
    const float* mlp = (const float*)d_in[0];  // [B,N,31]
    const float* cd  = (const float*)d_in[1];  // [B,N,32,2]
    const float* sig = (const float*)d_in[2];  // [32]
    const float* gw  = (const float*)d_in[3];  // [B,N,32]
    const float* W   = (const float*)d_in[4];  // [32,6,31]

    int total  = in_sizes[3] / 32;             // B*N
    int blocks = (total + TILE_PTS - 1) / TILE_PTS;

    cudaFuncSetAttribute(hermite_gemm,
                         cudaFuncAttributeMaxDynamicSharedMemorySize, SMEM_BYTES);
    hermite_gemm<<<blocks, NT, SMEM_BYTES>>>(mlp, cd, sig, gw, W,
                                             (float*)d_out, total);
}

// round 3
// speedup vs baseline: 2.3318x; 2.3318x over previous
#include <cuda_runtime.h>
#include <stdint.h>

#define NT 256
#define TILE_PTS 128
#define KC 8                       // k-chunk size
#define NCHUNK (32 / KC)

// Packed f32x2 FMA — only reachable via PTX fma.rn.f32x2 (ptxas never emits FFMA2).
__device__ __forceinline__ unsigned long long fma2(unsigned long long a,
                                                   unsigned long long b,
                                                   unsigned long long c) {
    unsigned long long d;
    asm("fma.rn.f32x2 %0, %1, %2, %3;" : "=l"(d) : "l"(a), "l"(b), "l"(c));
    return d;
}

extern __shared__ __align__(16) float smem[];
// smem layout:
//   M  : [KC*6][128] float  @ 0      (24576 B) — monomial chunk, xor-swizzled cols
//   P2 : 192 rows x 16 ulonglong2    (49152 B) — folded weights, duplicated f32x2,
//        row chunk-permuted so P loads are 1-wavefront (see build loop)
//   stage[128][32] reuses the M region for the epilogue.
#define M_FLOATS (KC * 6 * TILE_PTS)
#define SMEM_BYTES (M_FLOATS * 4 + 192 * 32 * 8)

__global__ void __launch_bounds__(NT, 3)
hermite_gemm(const float* __restrict__ mlp,
             const float* __restrict__ cd,
             const float* __restrict__ sig,
             const float* __restrict__ gw,
             const float* __restrict__ W,
             float* __restrict__ out,
             int total /* B*N */) {
    float*      M   = smem;
    float2*     P2  = reinterpret_cast<float2*>(smem + M_FLOATS);
    ulonglong2* P2u = reinterpret_cast<ulonglong2*>(P2);

    const int tid   = threadIdx.x;
    const int tile0 = blockIdx.x * TILE_PTS;

    // ---- Build P (fold sigmas into rbf_weights; duplicate for f32x2) ----
    // Physical layout per row (32 float2 = 16 x 16B chunks):
    //   chunk pos = ((o>>1)&1)*8 + (o>>2)   -> lane og reads pv0 at chunk og
    //   (outputs 4og,4og+1) and pv1 at chunk 8+og (outputs 4og+2,4og+3).
    //   Consecutive og lanes hit consecutive 16B chunks => 1 LDS wavefront.
    for (int i = tid; i < 192 * 32; i += NT) {
        int o  = i & 31;
        int kj = i >> 5;
        int k  = kj / 6;
        int j  = kj - k * 6;
        float val = 0.0f;
        if (o < 31) {
            float s   = sig[k];
            float s2  = s * s;
            float is2 = 1.0f / (s2 + 1e-6f);
            float is4 = 1.0f / (s2 * s2 + 1e-6f);
            const float* Wk = W + k * 186 + o;      // [k][h][o], H=6, O=31
            if      (j == 0) val = Wk[0] - is2 * (Wk[93] + Wk[155]);
            else if (j == 1) val = -is2 * Wk[62];   // * g*dx
            else if (j == 2) val = -is2 * Wk[31];   // * g*dy
            else if (j == 3) val = is4 * Wk[155];   // * g*dx^2
            else if (j == 4) val = is4 * Wk[124];   // * g*dx*dy
            else             val = is4 * Wk[93];    // * g*dy^2
        }
        int pos = (((o >> 1) & 1) * 8 + (o >> 2)) * 2 + (o & 1);  // float2 slot
        P2[kj * 32 + pos] = make_float2(val, val);
    }

    const int og  = tid & 7;         // o-group: outputs og*4 .. og*4+3
    const int pg4 = (tid >> 3) * 4;  // first of 4 consecutive points

    unsigned long long acc[2][4];
#pragma unroll
    for (int pp = 0; pp < 2; pp++)
#pragma unroll
        for (int oo = 0; oo < 4; oo++) acc[pp][oo] = 0ull;

#pragma unroll 1
    for (int c = 0; c < NCHUNK; c++) {
        if (c > 0) __syncthreads();   // previous chunk's M reads done

        // ---- Phase 1: monomials for k in [c*KC, c*KC+KC) ----
        // item -> (pt, kl); lanes traverse kl => coalesced gmem segments.
        // STS col = pt ^ (kl<<2): 32 lanes hit 32 distinct banks.
#pragma unroll
        for (int it = 0; it < (TILE_PTS * KC) / NT; it++) {   // 4 iters
            int item = tid + it * NT;
            int kl   = item & (KC - 1);
            int pt   = item >> 3;
            int n    = tile0 + pt;
            int k    = c * KC + kl;
            float dx = 0.0f, dy = 0.0f, g = 0.0f;
            if (n < total) {
                float2 cc = reinterpret_cast<const float2*>(cd)[(size_t)n * 32 + k];
                dx = cc.x; dy = cc.y;
                g  = gw[(size_t)n * 32 + k];
            }
            float m1 = g * dx, m2 = g * dy;
            float* Mr = M + (kl * 6) * TILE_PTS + (pt ^ (kl << 2));
            Mr[0 * TILE_PTS] = g;
            Mr[1 * TILE_PTS] = m1;
            Mr[2 * TILE_PTS] = m2;
            Mr[3 * TILE_PTS] = m1 * dx;
            Mr[4 * TILE_PTS] = m1 * dy;
            Mr[5 * TILE_PTS] = m2 * dy;
        }
        __syncthreads();

        // ---- Phase 2: 4 pts x 4 outs per thread over this chunk ----
#pragma unroll 2
        for (int kl = 0; kl < KC; kl++) {
            const float* Mk = M + (kl * 6) * TILE_PTS + (pg4 ^ (kl << 2));
            const ulonglong2* Pk = P2u + ((c * KC + kl) * 6) * 16 + og;
#pragma unroll
            for (int j = 0; j < 6; j++) {
                // 4 consecutive points = two pre-packed f32x2 pairs.
                ulonglong2 mv  = *reinterpret_cast<const ulonglong2*>(Mk + j * TILE_PTS);
                ulonglong2 pv0 = Pk[j * 16];        // chunk og   : outs 4og,4og+1
                ulonglong2 pv1 = Pk[j * 16 + 8];    // chunk 8+og : outs 4og+2,4og+3
                acc[0][0] = fma2(mv.x, pv0.x, acc[0][0]);
                acc[0][1] = fma2(mv.x, pv0.y, acc[0][1]);
                acc[0][2] = fma2(mv.x, pv1.x, acc[0][2]);
                acc[0][3] = fma2(mv.x, pv1.y, acc[0][3]);
                acc[1][0] = fma2(mv.y, pv0.x, acc[1][0]);
                acc[1][1] = fma2(mv.y, pv0.y, acc[1][1]);
                acc[1][2] = fma2(mv.y, pv1.x, acc[1][2]);
                acc[1][3] = fma2(mv.y, pv1.y, acc[1][3]);
            }
        }
    }

    // ---- Epilogue: stage mix into dead M region, then coalesced I/O ----
    __syncthreads();
    float* stage = M;  // [128][32] = 16KB <= 24KB M region
#pragma unroll
    for (int pp = 0; pp < 2; pp++)
#pragma unroll
        for (int oo = 0; oo < 4; oo++) {
            unsigned long long a = acc[pp][oo];
            float lo = __uint_as_float((unsigned)(a & 0xffffffffu));
            float hi = __uint_as_float((unsigned)(a >> 32));
            int o = og * 4 + oo;
            stage[(pg4 + 2 * pp)     * 32 + o] = lo;
            stage[(pg4 + 2 * pp + 1) * 32 + o] = hi;
        }
    __syncthreads();

    size_t lim  = (size_t)total * 31;
    size_t base = (size_t)tile0 * 31;
    for (int e = tid; e < TILE_PTS * 31; e += NT) {
        size_t gidx = base + e;
        if (gidx < lim) {
            int rr = e / 31;
            int o  = e - rr * 31;
            out[gidx] = mlp[gidx] * stage[rr * 32 + o];
        }
    }
}

extern "C" void kernel_launch(void* const* d_in, const int* in_sizes, int n_in,
                              void* d_out, int out_size) {
    const float* mlp = (const float*)d_in[0];  // [B,N,31]
    const float* cd  = (const float*)d_in[1];  // [B,N,32,2]
    const float* sig = (const float*)d_in[2];  // [32]
    const float* gw  = (const float*)d_in[3];  // [B,N,32]
    const float* W   = (const float*)d_in[4];  // [32,6,31]

    int total  = in_sizes[3] / 32;             // B*N
    int blocks = (total + TILE_PTS - 1) / TILE_PTS;

    cudaFuncSetAttribute(hermite_gemm,
                         cudaFuncAttributeMaxDynamicSharedMemorySize, SMEM_BYTES);
    hermite_gemm<<<blocks, NT, SMEM_BYTES>>>(mlp, cd, sig, gw, W,
                                             (float*)d_out, total);
}